// round 2
// baseline (speedup 1.0000x reference)
#include <cuda_runtime.h>

// Problem constants (fixed by the reference: B=4, C=32, H=64, W=64, NW=64)
#define NWC 64
#define HW_PIX 4096
#define CC 32

// Packed f32x2 FMA: d = a*b + c on two fp32 lanes in one FFMA2 instruction.
// Operands passed as scalar float pairs; mov.b64 pack/unpack is coalesced by
// ptxas into register pairs (zero-cost when allocation cooperates).
__device__ __forceinline__ void ffma2(float& dx, float& dy,
                                      float ax, float ay,
                                      float bx, float by,
                                      float cx, float cy) {
    asm("{\n\t"
        ".reg .b64 ra, rb, rc, rd;\n\t"
        "mov.b64 ra, {%2, %3};\n\t"
        "mov.b64 rb, {%4, %5};\n\t"
        "mov.b64 rc, {%6, %7};\n\t"
        "fma.rn.f32x2 rd, ra, rb, rc;\n\t"
        "mov.b64 {%0, %1}, rd;\n\t"
        "}"
        : "=f"(dx), "=f"(dy)
        : "f"(ax), "f"(ay), "f"(bx), "f"(by), "f"(cx), "f"(cy));
}

__device__ __forceinline__ float ex2(float a) {
    float r;
    asm("ex2.approx.ftz.f32 %0, %1;" : "=f"(r) : "f"(a));
    return r;
}

__global__ __launch_bounds__(256, 4)
void cplx_gaussian_rbf_kernel(
    const float* __restrict__ x_real, const float* __restrict__ x_imag,
    const float* __restrict__ w_real, const float* __restrict__ w_imag,
    const float* __restrict__ b_real, const float* __restrict__ b_imag,
    const float* __restrict__ mu_real, const float* __restrict__ mu_imag,
    const float* __restrict__ stddev,
    float* __restrict__ out)
{
    // Pre-duplicated coefficient tables so f32x2 operands load directly via
    // broadcast LDS.128 (no packing instructions in the hot loop).
    __shared__ float4 sA[NWC];  // {a0, a0, a1, a1}
    __shared__ float4 sB[NWC];  // {a2, a2, a3, a3}
    __shared__ float4 sW[NWC];  // {wr, wr, wi, wi}

    const int bc   = blockIdx.x >> 3;        // (b*C + c), 0..127
    const int tile = blockIdx.x & 7;         // 8 tiles of 512 pixels per (b,c)
    const int c    = bc & (CC - 1);
    const int tid  = threadIdx.x;

    if (tid < NWC) {
        const float LOG2E = 1.4426950408889634f;
        float mur = mu_real[tid];
        float mui = mu_imag[tid];
        // exp(-d2/(2*sigma)) = exp2( a0*s + a1*xr + a2*xi + a3 ),
        // s = xr^2+xi^2, cc = log2(e)/(2*sigma)
        float cc = LOG2E * 0.5f / stddev[tid];
        float a0 = -cc;
        float a1 = 2.0f * cc * mur;
        float a2 = 2.0f * cc * mui;
        float a3 = -cc * (mur * mur + mui * mui);
        sA[tid] = make_float4(a0, a0, a1, a1);
        sB[tid] = make_float4(a2, a2, a3, a3);
        float wr = w_real[c * NWC + tid];
        float wi = w_imag[c * NWC + tid];
        sW[tid] = make_float4(wr, wr, wi, wi);
    }
    __syncthreads();

    // Each thread handles two consecutive pixels (one float2 load, one float4 store).
    const int pairIdx = bc * (HW_PIX / 2) + tile * 256 + tid;  // in pixel-pair units
    const float2 xr = reinterpret_cast<const float2*>(x_real)[pairIdx];
    const float2 xi = reinterpret_cast<const float2*>(x_imag)[pairIdx];

    float sx = fmaf(xr.x, xr.x, xi.x * xi.x);
    float sy = fmaf(xr.y, xr.y, xi.y * xi.y);

    float accr_x = 0.0f, accr_y = 0.0f;
    float acci_x = 0.0f, acci_y = 0.0f;

#pragma unroll 16
    for (int n = 0; n < NWC; ++n) {
        const float4 A  = sA[n];   // a0,a0,a1,a1
        const float4 Bv = sB[n];   // a2,a2,a3,a3
        const float4 Wv = sW[n];   // wr,wr,wi,wi

        float gx, gy;
        // arg = a0*s + a3
        ffma2(gx, gy, sx, sy, A.x, A.y, Bv.z, Bv.w);
        // arg += a1*xr
        ffma2(gx, gy, xr.x, xr.y, A.z, A.w, gx, gy);
        // arg += a2*xi
        ffma2(gx, gy, xi.x, xi.y, Bv.x, Bv.y, gx, gy);

        float rx = ex2(gx);
        float ry = ex2(gy);

        ffma2(accr_x, accr_y, rx, ry, Wv.x, Wv.y, accr_x, accr_y);
        ffma2(acci_x, acci_y, rx, ry, Wv.z, Wv.w, acci_x, acci_y);
    }

    const float br = b_real[c];
    const float bi = b_imag[c];

    // Output layout (B,C,H,W,2): pixel pair -> 4 consecutive floats (r0,i0,r1,i1).
    float4 o;
    o.x = accr_x + br;
    o.y = acci_x + bi;
    o.z = accr_y + br;
    o.w = acci_y + bi;
    reinterpret_cast<float4*>(out)[pairIdx] = o;
}

extern "C" void kernel_launch(void* const* d_in, const int* in_sizes, int n_in,
                              void* d_out, int out_size) {
    const float* x_real  = (const float*)d_in[0];
    const float* x_imag  = (const float*)d_in[1];
    const float* w_real  = (const float*)d_in[2];
    const float* w_imag  = (const float*)d_in[3];
    const float* b_real  = (const float*)d_in[4];
    const float* b_imag  = (const float*)d_in[5];
    const float* mu_real = (const float*)d_in[6];
    const float* mu_imag = (const float*)d_in[7];
    const float* stddev  = (const float*)d_in[8];
    float* out = (float*)d_out;

    // grid: 128 (b,c) pairs * 8 tiles = 1024 blocks; 256 threads; 2 pixels/thread
    cplx_gaussian_rbf_kernel<<<1024, 256>>>(
        x_real, x_imag, w_real, w_imag, b_real, b_imag,
        mu_real, mu_imag, stddev, out);
}

// round 3
// speedup vs baseline: 1.1189x; 1.1189x over previous
#include <cuda_runtime.h>

// Problem constants (fixed by the reference: B=4, C=32, H=64, W=64, NW=64)
#define NWC 64
#define HW_PIX 4096
#define CC 32

// Packed f32x2 FMA: d = a*b + c on two fp32 lanes in one FFMA2 instruction.
__device__ __forceinline__ void ffma2(float& dx, float& dy,
                                      float ax, float ay,
                                      float bx, float by,
                                      float cx, float cy) {
    asm("{\n\t"
        ".reg .b64 ra, rb, rc, rd;\n\t"
        "mov.b64 ra, {%2, %3};\n\t"
        "mov.b64 rb, {%4, %5};\n\t"
        "mov.b64 rc, {%6, %7};\n\t"
        "fma.rn.f32x2 rd, ra, rb, rc;\n\t"
        "mov.b64 {%0, %1}, rd;\n\t"
        "}"
        : "=f"(dx), "=f"(dy)
        : "f"(ax), "f"(ay), "f"(bx), "f"(by), "f"(cx), "f"(cy));
}

__device__ __forceinline__ float ex2(float a) {
    float r;
    asm("ex2.approx.ftz.f32 %0, %1;" : "=f"(r) : "f"(a));
    return r;
}

__global__ __launch_bounds__(128)
void cplx_gaussian_rbf_kernel(
    const float* __restrict__ x_real, const float* __restrict__ x_imag,
    const float* __restrict__ w_real, const float* __restrict__ w_imag,
    const float* __restrict__ b_real, const float* __restrict__ b_imag,
    const float* __restrict__ mu_real, const float* __restrict__ mu_imag,
    const float* __restrict__ stddev,
    float* __restrict__ out)
{
    // Pre-duplicated coefficient tables: f32x2 operands come straight from
    // broadcast LDS.128, amortized over 8 pixels per thread.
    __shared__ float4 sA[NWC];  // {a0, a0, a1, a1}
    __shared__ float4 sB[NWC];  // {a2, a2, a3, a3}
    __shared__ float4 sW[NWC];  // {wr, wr, wi, wi}

    const int bc   = blockIdx.x >> 2;        // (b*C + c), 0..127
    const int tile = blockIdx.x & 3;         // 4 tiles of 1024 pixels per (b,c)
    const int c    = bc & (CC - 1);
    const int tid  = threadIdx.x;

    if (tid < NWC) {
        const float LOG2E = 1.4426950408889634f;
        float mur = mu_real[tid];
        float mui = mu_imag[tid];
        // exp(-d2/(2*sigma)) = exp2( a0*s + a1*xr + a2*xi + a3 ),
        // s = xr^2+xi^2, cc = log2(e)/(2*sigma)
        float cc = LOG2E * 0.5f / stddev[tid];
        float a0 = -cc;
        float a1 = 2.0f * cc * mur;
        float a2 = 2.0f * cc * mui;
        float a3 = -cc * (mur * mur + mui * mui);
        sA[tid] = make_float4(a0, a0, a1, a1);
        sB[tid] = make_float4(a2, a2, a3, a3);
        float wr = w_real[c * NWC + tid];
        float wi = w_imag[c * NWC + tid];
        sW[tid] = make_float4(wr, wr, wi, wi);
    }
    __syncthreads();

    // 8 consecutive pixels per thread (= 4 pixel-pairs).
    const int pairBase = bc * (HW_PIX / 2) + tile * 512 + tid * 4;  // pixel-pair units
    const int f4base   = pairBase >> 1;                              // float4 units

    const float4 xr0 = reinterpret_cast<const float4*>(x_real)[f4base];
    const float4 xr1 = reinterpret_cast<const float4*>(x_real)[f4base + 1];
    const float4 xi0 = reinterpret_cast<const float4*>(x_imag)[f4base];
    const float4 xi1 = reinterpret_cast<const float4*>(x_imag)[f4base + 1];

    float xr[8] = {xr0.x, xr0.y, xr0.z, xr0.w, xr1.x, xr1.y, xr1.z, xr1.w};
    float xi[8] = {xi0.x, xi0.y, xi0.z, xi0.w, xi1.x, xi1.y, xi1.z, xi1.w};

    float s[8];
#pragma unroll
    for (int k = 0; k < 8; ++k)
        s[k] = fmaf(xr[k], xr[k], xi[k] * xi[k]);

    float accr[8], acci[8];
#pragma unroll
    for (int k = 0; k < 8; ++k) { accr[k] = 0.0f; acci[k] = 0.0f; }

#pragma unroll 4
    for (int n = 0; n < NWC; ++n) {
        const float4 A  = sA[n];   // a0,a0,a1,a1
        const float4 Bv = sB[n];   // a2,a2,a3,a3
        const float4 Wv = sW[n];   // wr,wr,wi,wi

#pragma unroll
        for (int k = 0; k < 8; k += 2) {
            float gx, gy;
            // arg = a0*s + a3
            ffma2(gx, gy, s[k], s[k+1], A.x, A.y, Bv.z, Bv.w);
            // arg += a1*xr
            ffma2(gx, gy, xr[k], xr[k+1], A.z, A.w, gx, gy);
            // arg += a2*xi
            ffma2(gx, gy, xi[k], xi[k+1], Bv.x, Bv.y, gx, gy);

            float rx = ex2(gx);
            float ry = ex2(gy);

            ffma2(accr[k], accr[k+1], rx, ry, Wv.x, Wv.y, accr[k], accr[k+1]);
            ffma2(acci[k], acci[k+1], rx, ry, Wv.z, Wv.w, acci[k], acci[k+1]);
        }
    }

    const float br = b_real[c];
    const float bi = b_imag[c];

    // Output layout (B,C,H,W,2): each pixel-pair -> one float4 (r0,i0,r1,i1).
    float4* out4 = reinterpret_cast<float4*>(out);
#pragma unroll
    for (int k = 0; k < 4; ++k) {
        float4 o;
        o.x = accr[2*k]     + br;
        o.y = acci[2*k]     + bi;
        o.z = accr[2*k + 1] + br;
        o.w = acci[2*k + 1] + bi;
        out4[pairBase + k] = o;
    }
}

extern "C" void kernel_launch(void* const* d_in, const int* in_sizes, int n_in,
                              void* d_out, int out_size) {
    const float* x_real  = (const float*)d_in[0];
    const float* x_imag  = (const float*)d_in[1];
    const float* w_real  = (const float*)d_in[2];
    const float* w_imag  = (const float*)d_in[3];
    const float* b_real  = (const float*)d_in[4];
    const float* b_imag  = (const float*)d_in[5];
    const float* mu_real = (const float*)d_in[6];
    const float* mu_imag = (const float*)d_in[7];
    const float* stddev  = (const float*)d_in[8];
    float* out = (float*)d_out;

    // 128 (b,c) pairs * 4 tiles = 512 blocks; 128 threads; 8 pixels/thread
    cplx_gaussian_rbf_kernel<<<512, 128>>>(
        x_real, x_imag, w_real, w_imag, b_real, b_imag,
        mu_real, mu_imag, stddev, out);
}

// round 4
// speedup vs baseline: 1.1507x; 1.0284x over previous
#include <cuda_runtime.h>

// Problem constants (fixed by the reference: B=4, C=32, H=64, W=64, NW=64)
#define NWC 64
#define HW_PIX 4096
#define CC 32

// Packed f32x2 FMA: d = a*b + c on two fp32 lanes in one FFMA2 instruction.
__device__ __forceinline__ void ffma2(float& dx, float& dy,
                                      float ax, float ay,
                                      float bx, float by,
                                      float cx, float cy) {
    asm("{\n\t"
        ".reg .b64 ra, rb, rc, rd;\n\t"
        "mov.b64 ra, {%2, %3};\n\t"
        "mov.b64 rb, {%4, %5};\n\t"
        "mov.b64 rc, {%6, %7};\n\t"
        "fma.rn.f32x2 rd, ra, rb, rc;\n\t"
        "mov.b64 {%0, %1}, rd;\n\t"
        "}"
        : "=f"(dx), "=f"(dy)
        : "f"(ax), "f"(ay), "f"(bx), "f"(by), "f"(cx), "f"(cy));
}

__device__ __forceinline__ float ex2(float a) {
    float r;
    asm("ex2.approx.ftz.f32 %0, %1;" : "=f"(r) : "f"(a));
    return r;
}

__global__ __launch_bounds__(128)
void cplx_gaussian_rbf_kernel(
    const float* __restrict__ x_real, const float* __restrict__ x_imag,
    const float* __restrict__ w_real, const float* __restrict__ w_imag,
    const float* __restrict__ b_real, const float* __restrict__ b_imag,
    const float* __restrict__ mu_real, const float* __restrict__ mu_imag,
    const float* __restrict__ stddev,
    float* __restrict__ out)
{
    // Pre-duplicated coefficient tables: f32x2 operands come straight from
    // broadcast LDS.128, amortized over 4 pixels per thread.
    __shared__ float4 sA[NWC];  // {a0, a0, a1, a1}
    __shared__ float4 sB[NWC];  // {a2, a2, a3, a3}
    __shared__ float4 sW[NWC];  // {wr, wr, wi, wi}

    const int bc   = blockIdx.x >> 3;        // (b*C + c), 0..127
    const int tile = blockIdx.x & 7;         // 8 tiles of 512 pixels per (b,c)
    const int c    = bc & (CC - 1);
    const int tid  = threadIdx.x;

    if (tid < NWC) {
        const float LOG2E = 1.4426950408889634f;
        float mur = mu_real[tid];
        float mui = mu_imag[tid];
        // exp(-d2/(2*sigma)) = exp2( a0*s + a1*xr + a2*xi + a3 ),
        // s = xr^2+xi^2, cc = log2(e)/(2*sigma)
        float cc = LOG2E * 0.5f / stddev[tid];
        float a0 = -cc;
        float a1 = 2.0f * cc * mur;
        float a2 = 2.0f * cc * mui;
        float a3 = -cc * (mur * mur + mui * mui);
        sA[tid] = make_float4(a0, a0, a1, a1);
        sB[tid] = make_float4(a2, a2, a3, a3);
        float wr = w_real[c * NWC + tid];
        float wi = w_imag[c * NWC + tid];
        sW[tid] = make_float4(wr, wr, wi, wi);
    }
    __syncthreads();

    // 4 consecutive pixels per thread (= 2 pixel-pairs = 1 float4 per input).
    const int f4idx    = bc * (HW_PIX / 4) + tile * 128 + tid;  // float4 units
    const int pairBase = f4idx * 2;                              // pixel-pair units

    const float4 xr4 = reinterpret_cast<const float4*>(x_real)[f4idx];
    const float4 xi4 = reinterpret_cast<const float4*>(x_imag)[f4idx];

    float xr[4] = {xr4.x, xr4.y, xr4.z, xr4.w};
    float xi[4] = {xi4.x, xi4.y, xi4.z, xi4.w};

    float s[4];
#pragma unroll
    for (int k = 0; k < 4; ++k)
        s[k] = fmaf(xr[k], xr[k], xi[k] * xi[k]);

    float accr[4], acci[4];
#pragma unroll
    for (int k = 0; k < 4; ++k) { accr[k] = 0.0f; acci[k] = 0.0f; }

#pragma unroll 8
    for (int n = 0; n < NWC; ++n) {
        const float4 A  = sA[n];   // a0,a0,a1,a1
        const float4 Bv = sB[n];   // a2,a2,a3,a3
        const float4 Wv = sW[n];   // wr,wr,wi,wi

#pragma unroll
        for (int k = 0; k < 4; k += 2) {
            float gx, gy;
            // arg = a0*s + a3
            ffma2(gx, gy, s[k], s[k+1], A.x, A.y, Bv.z, Bv.w);
            // arg += a1*xr
            ffma2(gx, gy, xr[k], xr[k+1], A.z, A.w, gx, gy);
            // arg += a2*xi
            ffma2(gx, gy, xi[k], xi[k+1], Bv.x, Bv.y, gx, gy);

            float rx = ex2(gx);
            float ry = ex2(gy);

            ffma2(accr[k], accr[k+1], rx, ry, Wv.x, Wv.y, accr[k], accr[k+1]);
            ffma2(acci[k], acci[k+1], rx, ry, Wv.z, Wv.w, acci[k], acci[k+1]);
        }
    }

    const float br = b_real[c];
    const float bi = b_imag[c];

    // Output layout (B,C,H,W,2): each pixel-pair -> one float4 (r0,i0,r1,i1).
    float4* out4 = reinterpret_cast<float4*>(out);
#pragma unroll
    for (int k = 0; k < 2; ++k) {
        float4 o;
        o.x = accr[2*k]     + br;
        o.y = acci[2*k]     + bi;
        o.z = accr[2*k + 1] + br;
        o.w = acci[2*k + 1] + bi;
        out4[pairBase + k] = o;
    }
}

extern "C" void kernel_launch(void* const* d_in, const int* in_sizes, int n_in,
                              void* d_out, int out_size) {
    const float* x_real  = (const float*)d_in[0];
    const float* x_imag  = (const float*)d_in[1];
    const float* w_real  = (const float*)d_in[2];
    const float* w_imag  = (const float*)d_in[3];
    const float* b_real  = (const float*)d_in[4];
    const float* b_imag  = (const float*)d_in[5];
    const float* mu_real = (const float*)d_in[6];
    const float* mu_imag = (const float*)d_in[7];
    const float* stddev  = (const float*)d_in[8];
    float* out = (float*)d_out;

    // 128 (b,c) pairs * 8 tiles = 1024 blocks; 128 threads; 4 pixels/thread
    cplx_gaussian_rbf_kernel<<<1024, 128>>>(
        x_real, x_imag, w_real, w_imag, b_real, b_imag,
        mu_real, mu_imag, stddev, out);
}